// round 12
// baseline (speedup 1.0000x reference)
#include <cuda_runtime.h>
#include <cuda_bf16.h>
#include <cstdint>
#include <math.h>

// ---------------- device scratch ----------------
__device__ __nv_bfloat16 g_h1b[33554432];      // [32,128,128,64] NHWC bf16
__device__ __nv_bfloat16 g_h2b[16777216];      // [32,64,64,128]  NHWC bf16
__device__ float  g_z  [8388608];              // [32,64,64,64] fp32 (VQ/loss path)
__device__ __nv_bfloat16 g_qb [8388608];       // q bf16 (decoder input)
__device__ __nv_bfloat16 g_d1b[67108864];      // [32,128,128,128] bf16
__device__ __nv_bfloat16 g_d2b[134217728];     // [32,256,256,64]  bf16
__device__ float  g_col[25165824];             // L1 im2col (fp32)
__device__ float  g_wb1[3072];
__device__ __nv_bfloat16 g_wb2b[131072];
__device__ __nv_bfloat16 g_wb3b[73728];
__device__ __nv_bfloat16 g_wbd1[131072];       // 4 parities x 32768
__device__ __nv_bfloat16 g_wbd2[131072];       // 4 parities x 32768
__device__ float  g_enorm[512];
__device__ double g_loss;

__device__ __forceinline__ uint32_t smem_u32(const void* p) {
    uint32_t a;
    asm("{ .reg .u64 t; cvta.to.shared.u64 t, %1; cvt.u32.u64 %0, t; }" : "=r"(a) : "l"(p));
    return a;
}
__device__ __forceinline__ uint32_t swz(uint32_t off) { return off ^ ((off >> 3) & 0x70); }
__device__ __forceinline__ void cpa16(uint32_t dst, const void* src, bool ok) {
    asm volatile("cp.async.cg.shared.global [%0], [%1], 16, %2;"
                 :: "r"(dst), "l"(src), "r"(ok ? 16 : 0) : "memory");
}
__device__ __forceinline__ void cpa_commit() {
    asm volatile("cp.async.commit_group;" ::: "memory");
}
template<int N>
__device__ __forceinline__ void cpa_wait() {
    asm volatile("cp.async.wait_group %0;" :: "n"(N) : "memory");
}

// ---------------- pack_all ----------------
__global__ void __launch_bounds__(256)
pack_all(const float* __restrict__ w1, const float* __restrict__ w2,
         const float* __restrict__ w3, const float* __restrict__ dw1,
         const float* __restrict__ dw2, const float* __restrict__ emb) {
    long idx = (long)blockIdx.x * 256 + threadIdx.x;
    if (idx < 3072) {
        int co = (int)idx / 48, rem = (int)idx % 48;
        int ci = rem / 16, r2 = rem % 16;
        g_wb1[co * 48 + r2 * 3 + ci] = w1[idx];
        return;
    }
    idx -= 3072;
    if (idx < 131072) {
        int co = (int)idx >> 10, rem = (int)idx & 1023;
        int ci = rem >> 4, r2 = rem & 15;
        g_wb2b[co * 1024 + r2 * 64 + ci] = __float2bfloat16(w2[idx]);
        return;
    }
    idx -= 131072;
    if (idx < 73728) {
        int co = (int)idx / 1152, rem = (int)idx % 1152;
        int ci = rem / 9, r2 = rem % 9;
        g_wb3b[co * 1152 + r2 * 128 + ci] = __float2bfloat16(w3[idx]);
        return;
    }
    idx -= 73728;
    if (idx < 131072) {
        int p = (int)idx >> 15, local = (int)idx & 32767;
        int py = p >> 1, px = p & 1;
        int co = local >> 8, rem = local & 255;
        int ci = rem >> 2, tt = rem & 3;
        int ky = (1 - py) + 2 * (tt >> 1), kx = (1 - px) + 2 * (tt & 1);
        g_wbd1[p * 32768 + co * 256 + tt * 64 + ci] =
            __float2bfloat16(dw1[(((long)ci * 128 + co) * 4 + ky) * 4 + kx]);
        return;
    }
    idx -= 131072;
    if (idx < 131072) {
        int p = (int)idx >> 15, local = (int)idx & 32767;
        int py = p >> 1, px = p & 1;
        int co = local >> 9, rem = local & 511;
        int ci = rem >> 2, tt = rem & 3;
        int ky = (1 - py) + 2 * (tt >> 1), kx = (1 - px) + 2 * (tt & 1);
        g_wbd2[p * 32768 + co * 512 + tt * 128 + ci] =
            __float2bfloat16(dw2[(((long)ci * 64 + co) * 4 + ky) * 4 + kx]);
        return;
    }
    idx -= 131072;
    if (idx < 512) {
        float s = 0.f;
        const float* e = emb + idx * 64;
#pragma unroll 8
        for (int d = 0; d < 64; ++d) { float v = e[d]; s = fmaf(v, v, s); }
        g_enorm[idx] = s;
        return;
    }
    if (idx == 512) g_loss = 0.0;
}

__global__ void finalize_loss(float* out, long pos) {
    out[pos] = (float)(1.25 * g_loss / 8388608.0);
}

// ---------------- L1 im2col reading x NCHW directly ----------------
__global__ void __launch_bounds__(256)
im2col_l1(const float* __restrict__ x, float* __restrict__ col) {
    int mi = threadIdx.x >> 4, kt = threadIdx.x & 15;
    int m = blockIdx.x * 16 + mi;
    int n = m >> 14;
    int r = m & 16383;
    int oy = r >> 7, ox = r & 127;
    const float* xb = x + (long)n * 196608;
    float* colr = col + (long)m * 48;
    for (int k = kt; k < 48; k += 16) {
        int ci = k % 3, t = k / 3;
        int kx = t & 3, ky = t >> 2;
        int iy = oy * 2 - 1 + ky, ix = ox * 2 - 1 + kx;
        float v = 0.f;
        if (iy >= 0 && iy < 256 && ix >= 0 && ix < 256)
            v = xb[((long)ci << 16) + iy * 256 + ix];
        colr[k] = v;
    }
}

// ---------------- A-tile loaders ----------------
struct DenseLoader {
    const float* A; int ldk;
    const float* p;
    __device__ void init(int m) { p = A + (long)m * ldk; }
    __device__ void load8(int k, float4& a0, float4& a1) const {
        a0 = *(const float4*)(p + k);
        a1 = *(const float4*)(p + k + 4);
    }
};

// addr() of a 64-k segment; stays inside one (ky,kx) tap (64 | CIN).
template<int CIN, int KH, int KW, int ST, int PAD, int IH, int IW, int OW>
struct ConvLoaderB {
    const __nv_bfloat16* in;
    const __nv_bfloat16* base; int oy, ox;
    __device__ void init(int m) {
        int n = m / (OW * OW);
        int r = m % (OW * OW);
        oy = r / OW; ox = r % OW;
        base = in + (long)n * IH * IW * CIN;
    }
    __device__ const __nv_bfloat16* addr(int k, bool& ok) const {
        int ci = k % CIN, t = k / CIN;
        int ky = t / KW, kx = t % KW;
        int iy = oy * ST - PAD + ky, ix = ox * ST - PAD + kx;
        ok = (iy >= 0 && iy < IH && ix >= 0 && ix < IW);
        return ok ? base + ((long)iy * IW + ix) * CIN + ci : base;
    }
};

template<int CIN, int IH, int IW>
struct DeconvLoaderB {
    const __nv_bfloat16* in; int py, px;
    const __nv_bfloat16* base; int u, v;
    __device__ void init(int m) {
        int n = m / (IH * IW);
        int r = m % (IH * IW);
        u = r / IW; v = r % IW;
        base = in + (long)n * IH * IW * CIN;
    }
    __device__ const __nv_bfloat16* addr(int k, bool& ok) const {
        int ci = k % CIN, t = k / CIN;
        int iy = u + py - (t >> 1), ix = v + px - (t & 1);
        ok = (iy >= 0 && iy < IH && ix >= 0 && ix < IW);
        return ok ? base + ((long)iy * IW + ix) * CIN + ci : base;
    }
};

// ---------------- epilogue descriptor ----------------
struct Epi {
    float* out; const float* bias;
    int mode, act, ldc;
    int MPN, OV, W2, C, py, px;
    long nstride;
};

__device__ __forceinline__ long epi_base(const Epi& ep, int m) {
    if (ep.mode == 0) return (long)m * ep.ldc;
    int nn = m / ep.MPN, r = m % ep.MPN;
    int u = r / ep.OV, v = r % ep.OV;
    return (long)nn * ep.nstride +
           ((long)(2*u + ep.py) * ep.W2 + (2*v + ep.px)) * ep.C;
}

// ---------------- fp32 SGEMM (L1 only), bf16 output ----------------
template<class LD>
__global__ void __launch_bounds__(256)
sgemm_t(LD ld, const float* __restrict__ Bm, int K, Epi ep, __nv_bfloat16* outb) {
    __shared__ float As[16][132];
    __shared__ float Bs[16][68];
    const int tid = threadIdx.x;
    const int m0 = blockIdx.y * 128, n0 = blockIdx.x * 64;
    const int tx = tid & 15, ty = tid >> 4;
    const int ra = tid >> 1, ca = (tid & 1) * 8;
    const int rb = tid >> 2, cb = (tid & 3) * 4;
    float acc[8][4] = {};
    ld.init(m0 + ra);
    const float* Bptr = Bm + (long)(n0 + rb) * K + cb;

    for (int k0 = 0; k0 < K; k0 += 16) {
        float4 a0, a1;
        ld.load8(k0 + ca, a0, a1);
        float4 b0 = *(const float4*)(Bptr + k0);
        As[ca+0][ra]=a0.x; As[ca+1][ra]=a0.y; As[ca+2][ra]=a0.z; As[ca+3][ra]=a0.w;
        As[ca+4][ra]=a1.x; As[ca+5][ra]=a1.y; As[ca+6][ra]=a1.z; As[ca+7][ra]=a1.w;
        Bs[cb+0][rb]=b0.x; Bs[cb+1][rb]=b0.y; Bs[cb+2][rb]=b0.z; Bs[cb+3][rb]=b0.w;
        __syncthreads();
#pragma unroll
        for (int kk = 0; kk < 16; ++kk) {
            float4 aA = *(const float4*)&As[kk][ty*8];
            float4 aB = *(const float4*)&As[kk][ty*8+4];
            float4 bb = *(const float4*)&Bs[kk][tx*4];
            float av[8] = {aA.x,aA.y,aA.z,aA.w,aB.x,aB.y,aB.z,aB.w};
            float bv[4] = {bb.x,bb.y,bb.z,bb.w};
#pragma unroll
            for (int i = 0; i < 8; ++i)
#pragma unroll
                for (int j = 0; j < 4; ++j)
                    acc[i][j] = fmaf(av[i], bv[j], acc[i][j]);
        }
        __syncthreads();
    }

    const int n_base = n0 + tx * 4;
    float bvals[4];
#pragma unroll
    for (int j = 0; j < 4; ++j) bvals[j] = ep.bias ? ep.bias[n_base + j] : 0.f;
#pragma unroll
    for (int i = 0; i < 8; ++i) {
        int m = m0 + ty * 8 + i;
        long base = (long)m * ep.ldc + n_base;
        float v0 = fmaxf(acc[i][0] + bvals[0], 0.f);
        float v1 = fmaxf(acc[i][1] + bvals[1], 0.f);
        float v2 = fmaxf(acc[i][2] + bvals[2], 0.f);
        float v3 = fmaxf(acc[i][3] + bvals[3], 0.f);
        __nv_bfloat162 p0 = __floats2bfloat162_rn(v0, v1);
        __nv_bfloat162 p1 = __floats2bfloat162_rn(v2, v3);
        uint2 u; u.x = *(uint32_t*)&p0; u.y = *(uint32_t*)&p1;
        *(uint2*)(outb + base) = u;
    }
}

// ---------------- HMMA bf16 GEMM v3: 64x64 warp tiles, 4 warps, 3-stage cp.async ----
// TN=128: CTA 128x128 (warps 2m x 2n). TN=64: CTA 256x64 (warps 4m x 1n).
template<class LD, int TN, int MT, bool OBF>
__global__ void __launch_bounds__(128)
hgemm3(LD ld, const __nv_bfloat16* __restrict__ Bw, int K, Epi ep) {
    constexpr int RPT  = MT / 128;              // A rows per thread
    constexpr int NWN  = TN / 64;               // warps along n
    constexpr int NBC  = TN / 16;               // B cpa16 per thread
    constexpr uint32_t ABUF = (uint32_t)MT * 128;
    constexpr uint32_t BBUF = (uint32_t)TN * 128;
    constexpr uint32_t STG  = ABUF + BBUF;
    extern __shared__ char dynsm[];
    const uint32_t s0 = smem_u32(dynsm);

    const int tid = threadIdx.x;
    const int wid = tid >> 5, lane = tid & 31;
    const int m0 = blockIdx.y * MT;
    const int wm = (wid / NWN) * 64;
    const int wn = (wid % NWN) * 64;

    LD lds[RPT];
#pragma unroll
    for (int rr = 0; rr < RPT; ++rr) {
        lds[rr] = ld;
        lds[rr].init(m0 + tid + rr * 128);
    }

    float acc[4][8][4];
#pragma unroll
    for (int i = 0; i < 4; ++i)
#pragma unroll
        for (int j = 0; j < 8; ++j)
#pragma unroll
            for (int c = 0; c < 4; ++c) acc[i][j][c] = 0.f;

    auto fill = [&](int k0, int st) {
        uint32_t aDst = s0 + st * STG;
#pragma unroll
        for (int rr = 0; rr < RPT; ++rr) {
            bool ok;
            const __nv_bfloat16* p = lds[rr].addr(k0, ok);
            uint32_t rowi = (uint32_t)(tid + rr * 128);
#pragma unroll
            for (int j = 0; j < 8; ++j)
                cpa16(aDst + swz(rowi * 128 + j * 16), p + j * 8, ok);
        }
        uint32_t bDst = aDst + ABUF;
#pragma unroll
        for (int c = 0; c < NBC; ++c) {
            int i = c * 128 + tid;
            int r = i >> 3, sg = i & 7;
            cpa16(bDst + swz((uint32_t)r * 128 + sg * 16),
                  Bw + (long)r * K + k0 + sg * 8, true);
        }
    };

    fill(0, 0);  cpa_commit();
    fill(64, 1); cpa_commit();

    int st = 0;
    for (int k0 = 0; k0 < K; k0 += 64) {
        cpa_wait<1>();
        __syncthreads();
        if (k0 + 128 < K) {
            int nst = st + 2; if (nst >= 3) nst -= 3;
            fill(k0 + 128, nst);
        }
        cpa_commit();

        const uint32_t aBase = s0 + st * STG;
        const uint32_t bBase = aBase + ABUF;
#pragma unroll
        for (int ks = 0; ks < 4; ++ks) {
            const uint32_t kb = ks * 32 + (lane >> 4) * 16;
            uint32_t af[4][4];
#pragma unroll
            for (int mi = 0; mi < 4; ++mi) {
                uint32_t r = wm + mi * 16 + (lane & 15);
                uint32_t ad = aBase + swz(r * 128 + kb);
                asm volatile("ldmatrix.sync.aligned.m8n8.x4.shared.b16 {%0,%1,%2,%3}, [%4];"
                    : "=r"(af[mi][0]), "=r"(af[mi][1]), "=r"(af[mi][2]), "=r"(af[mi][3])
                    : "r"(ad));
            }
            uint32_t bf[4][4];
#pragma unroll
            for (int ni = 0; ni < 4; ++ni) {
                uint32_t r = wn + ni * 16 + (lane & 15);
                uint32_t ad = bBase + swz(r * 128 + kb);
                asm volatile("ldmatrix.sync.aligned.m8n8.x4.shared.b16 {%0,%1,%2,%3}, [%4];"
                    : "=r"(bf[ni][0]), "=r"(bf[ni][1]), "=r"(bf[ni][2]), "=r"(bf[ni][3])
                    : "r"(ad));
            }
#pragma unroll
            for (int mi = 0; mi < 4; ++mi)
#pragma unroll
                for (int ni = 0; ni < 4; ++ni) {
                    asm volatile(
                        "mma.sync.aligned.m16n8k16.row.col.f32.bf16.bf16.f32 "
                        "{%0,%1,%2,%3}, {%4,%5,%6,%7}, {%8,%9}, {%0,%1,%2,%3};"
                        : "+f"(acc[mi][2*ni][0]), "+f"(acc[mi][2*ni][1]),
                          "+f"(acc[mi][2*ni][2]), "+f"(acc[mi][2*ni][3])
                        : "r"(af[mi][0]), "r"(af[mi][1]), "r"(af[mi][2]), "r"(af[mi][3]),
                          "r"(bf[ni][0]), "r"(bf[ni][2]));
                    asm volatile(
                        "mma.sync.aligned.m16n8k16.row.col.f32.bf16.bf16.f32 "
                        "{%0,%1,%2,%3}, {%4,%5,%6,%7}, {%8,%9}, {%0,%1,%2,%3};"
                        : "+f"(acc[mi][2*ni+1][0]), "+f"(acc[mi][2*ni+1][1]),
                          "+f"(acc[mi][2*ni+1][2]), "+f"(acc[mi][2*ni+1][3])
                        : "r"(af[mi][0]), "r"(af[mi][1]), "r"(af[mi][2]), "r"(af[mi][3]),
                          "r"(bf[ni][1]), "r"(bf[ni][3]));
                }
        }
        st = (st == 2) ? 0 : st + 1;
    }

    const int col = wn + (lane & 3) * 2;
#pragma unroll
    for (int mi = 0; mi < 4; ++mi) {
        int m1 = m0 + wm + mi * 16 + (lane >> 2);
        long b1 = epi_base(ep, m1);
        long b2 = epi_base(ep, m1 + 8);
#pragma unroll
        for (int j = 0; j < 8; ++j) {
            int n = col + j * 8;
            float bi0 = ep.bias[n], bi1 = ep.bias[n + 1];
            float v0 = acc[mi][j][0] + bi0, v1 = acc[mi][j][1] + bi1;
            float v2 = acc[mi][j][2] + bi0, v3 = acc[mi][j][3] + bi1;
            if (ep.act) {
                v0 = fmaxf(v0, 0.f); v1 = fmaxf(v1, 0.f);
                v2 = fmaxf(v2, 0.f); v3 = fmaxf(v3, 0.f);
            }
            if (OBF) {
                __nv_bfloat16* ob = (__nv_bfloat16*)ep.out;
                __nv_bfloat162 p0 = __floats2bfloat162_rn(v0, v1);
                __nv_bfloat162 p1 = __floats2bfloat162_rn(v2, v3);
                *(uint32_t*)(ob + b1 + n) = *(uint32_t*)&p0;
                *(uint32_t*)(ob + b2 + n) = *(uint32_t*)&p1;
            } else {
                *(float2*)(ep.out + b1 + n) = make_float2(v0, v1);
                *(float2*)(ep.out + b2 + n) = make_float2(v2, v3);
            }
        }
    }
}

// ---------------- fused VQ: distances + argmin + gather(bf16) + loss ----------------
__global__ void __launch_bounds__(256)
vq_fused(const float* __restrict__ z, const float* __restrict__ emb,
         const float* __restrict__ enorm, __nv_bfloat16* __restrict__ qb) {
    __shared__ float4 se[16][16];
    __shared__ float sen[16];
    __shared__ float red[256];
    const int t = threadIdx.x;
    const long m = (long)blockIdx.x * 256 + t;
    float4 zr[16];
    const float4* zp = (const float4*)(z + m * 64);
#pragma unroll
    for (int i = 0; i < 16; ++i) zr[i] = zp[i];

    float best = 3.4e38f; int bidx = 0;
    const int ljj = t >> 4, ldd = t & 15;
    for (int j0 = 0; j0 < 512; j0 += 16) {
        __syncthreads();
        se[ljj][ldd] = ((const float4*)(emb + (long)(j0 + ljj) * 64))[ldd];
        if (t < 16) sen[t] = enorm[j0 + t];
        __syncthreads();
#pragma unroll
        for (int jj = 0; jj < 16; ++jj) {
            float s0 = 0.f, s1 = 0.f, s2 = 0.f, s3 = 0.f;
#pragma unroll
            for (int d = 0; d < 16; d += 4) {
                float4 e0 = se[jj][d+0], e1 = se[jj][d+1];
                float4 e2 = se[jj][d+2], e3 = se[jj][d+3];
                s0 = fmaf(zr[d+0].x, e0.x, s0); s0 = fmaf(zr[d+0].y, e0.y, s0);
                s0 = fmaf(zr[d+0].z, e0.z, s0); s0 = fmaf(zr[d+0].w, e0.w, s0);
                s1 = fmaf(zr[d+1].x, e1.x, s1); s1 = fmaf(zr[d+1].y, e1.y, s1);
                s1 = fmaf(zr[d+1].z, e1.z, s1); s1 = fmaf(zr[d+1].w, e1.w, s1);
                s2 = fmaf(zr[d+2].x, e2.x, s2); s2 = fmaf(zr[d+2].y, e2.y, s2);
                s2 = fmaf(zr[d+2].z, e2.z, s2); s2 = fmaf(zr[d+2].w, e2.w, s2);
                s3 = fmaf(zr[d+3].x, e3.x, s3); s3 = fmaf(zr[d+3].y, e3.y, s3);
                s3 = fmaf(zr[d+3].z, e3.z, s3); s3 = fmaf(zr[d+3].w, e3.w, s3);
            }
            float dist = sen[jj] - 2.f * ((s0 + s1) + (s2 + s3));
            if (dist < best) { best = dist; bidx = j0 + jj; }
        }
    }

    const float4* ep = (const float4*)(emb + (long)bidx * 64);
    uint2* qp = (uint2*)(qb + m * 64);
    float sq = 0.f;
#pragma unroll
    for (int i = 0; i < 16; ++i) {
        float4 e = ep[i];
        __nv_bfloat162 p0 = __floats2bfloat162_rn(e.x, e.y);
        __nv_bfloat162 p1 = __floats2bfloat162_rn(e.z, e.w);
        uint2 u; u.x = *(uint32_t*)&p0; u.y = *(uint32_t*)&p1;
        qp[i] = u;
        float d0 = e.x - zr[i].x, d1 = e.y - zr[i].y;
        float d2 = e.z - zr[i].z, d3 = e.w - zr[i].w;
        sq = fmaf(d0, d0, sq); sq = fmaf(d1, d1, sq);
        sq = fmaf(d2, d2, sq); sq = fmaf(d3, d3, sq);
    }
    red[t] = sq;
    __syncthreads();
    for (int s = 128; s; s >>= 1) {
        if (t < s) red[t] += red[t + s];
        __syncthreads();
    }
    if (t == 0) atomicAdd(&g_loss, (double)red[0]);
}

// ---------------- final deconv 64->3 k3 s1 p1 + sigmoid (bf16 in, NCHW fp32 out) ----------------
__global__ void __launch_bounds__(256)
deconv3_sigmoid(const __nv_bfloat16* __restrict__ in, const float* __restrict__ w,
                const float* __restrict__ bias, float* __restrict__ out) {
    __shared__ float sIn[8][18][66];
    __shared__ float sW[1728];
    const int t = threadIdx.x, n = blockIdx.z;
    const int y0 = blockIdx.y * 16, x0 = blockIdx.x * 64;
    for (int i = t; i < 1728; i += 256) sW[i] = w[i];
    const int ty = t >> 4, txq = t & 15;
    float acc[3][4] = {};
    for (int cc = 0; cc < 8; ++cc) {
        __syncthreads();
        for (int pos = t; pos < 18 * 66; pos += 256) {
            int sx = pos % 66, sy = pos / 66;
            int gy = y0 - 1 + sy, gx = x0 - 1 + sx;
            if (gy >= 0 && gy < 256 && gx >= 0 && gx < 256) {
                uint4 u = *(const uint4*)(in + (((long)n * 256 + gy) * 256 + gx) * 64 + cc * 8);
                float2 f0 = __bfloat1622float2(*(__nv_bfloat162*)&u.x);
                float2 f1 = __bfloat1622float2(*(__nv_bfloat162*)&u.y);
                float2 f2 = __bfloat1622float2(*(__nv_bfloat162*)&u.z);
                float2 f3 = __bfloat1622float2(*(__nv_bfloat162*)&u.w);
                sIn[0][sy][sx] = f0.x; sIn[1][sy][sx] = f0.y;
                sIn[2][sy][sx] = f1.x; sIn[3][sy][sx] = f1.y;
                sIn[4][sy][sx] = f2.x; sIn[5][sy][sx] = f2.y;
                sIn[6][sy][sx] = f3.x; sIn[7][sy][sx] = f3.y;
            } else {
#pragma unroll
                for (int c = 0; c < 8; ++c) sIn[c][sy][sx] = 0.f;
            }
        }
        __syncthreads();
#pragma unroll
        for (int c8 = 0; c8 < 8; ++c8) {
            const int ci = cc * 8 + c8;
#pragma unroll
            for (int ky = 0; ky < 3; ++ky)
#pragma unroll
            for (int kx = 0; kx < 3; ++kx) {
                const float* wp = &sW[ci*27 + ky*3 + kx];
                float w0 = wp[0], w1 = wp[9], w2 = wp[18];
                const float* ip = &sIn[c8][ty + 2 - ky][txq*4 + 2 - kx];
#pragma unroll
                for (int qq = 0; qq < 4; ++qq) {
                    float iv = ip[qq];
                    acc[0][qq] = fmaf(iv, w0, acc[0][qq]);
                    acc[1][qq] = fmaf(iv, w1, acc[1][qq]);
                    acc[2][qq] = fmaf(iv, w2, acc[2][qq]);
                }
            }
        }
    }
#pragma unroll
    for (int co = 0; co < 3; ++co) {
        float bb = bias[co];
#pragma unroll
        for (int qq = 0; qq < 4; ++qq) {
            float v = acc[co][qq] + bb;
            v = 1.f / (1.f + __expf(-v));
            out[(((long)n * 3 + co) * 256 + (y0 + ty)) * 256 + (x0 + txq*4 + qq)] = v;
        }
    }
}

// ---------------- host ----------------
static float* symaddr(const void* sym) {
    void* p = nullptr;
    cudaGetSymbolAddress(&p, sym);
    return (float*)p;
}

static Epi mk_row(float* out, const float* bias, int ldc, int act) {
    Epi e; e.out = out; e.bias = bias; e.mode = 0; e.act = act; e.ldc = ldc;
    e.MPN = e.OV = e.W2 = e.C = e.py = e.px = 0; e.nstride = 0; return e;
}
static Epi mk_dec(float* out, const float* bias, int MPN, int OV, int W2, int C,
                  int py, int px, long nstride, int act) {
    Epi e; e.out = out; e.bias = bias; e.mode = 1; e.act = act; e.ldc = 0;
    e.MPN = MPN; e.OV = OV; e.W2 = W2; e.C = C; e.py = py; e.px = px;
    e.nstride = nstride; return e;
}

typedef ConvLoaderB<64,4,4,2,1,128,128,64>   LdL2;
typedef ConvLoaderB<128,3,3,1,1,64,64,64>    LdL3;
typedef DeconvLoaderB<64,64,64>              LdD1;
typedef DeconvLoaderB<128,128,128>           LdD2;

extern "C" void kernel_launch(void* const* d_in, const int* in_sizes, int n_in,
                              void* d_out, int out_size) {
    const float* x   = (const float*)d_in[0];
    const float* w1  = (const float*)d_in[1];
    const float* b1  = (const float*)d_in[2];
    const float* w2  = (const float*)d_in[3];
    const float* b2  = (const float*)d_in[4];
    const float* w3  = (const float*)d_in[5];
    const float* b3  = (const float*)d_in[6];
    const float* emb = (const float*)d_in[7];
    const float* dw1 = (const float*)d_in[8];
    const float* db1 = (const float*)d_in[9];
    const float* dw2 = (const float*)d_in[10];
    const float* db2 = (const float*)d_in[11];
    const float* dw3 = (const float*)d_in[12];
    const float* db3 = (const float*)d_in[13];
    float* out = (float*)d_out;

    float* z   = symaddr(g_z);
    float* col = symaddr(g_col);
    float* wb1 = symaddr(g_wb1);
    float* en  = symaddr(g_enorm);
    __nv_bfloat16* h1b = (__nv_bfloat16*)symaddr(g_h1b);
    __nv_bfloat16* h2b = (__nv_bfloat16*)symaddr(g_h2b);
    __nv_bfloat16* qb  = (__nv_bfloat16*)symaddr(g_qb);
    __nv_bfloat16* d1b = (__nv_bfloat16*)symaddr(g_d1b);
    __nv_bfloat16* d2b = (__nv_bfloat16*)symaddr(g_d2b);
    __nv_bfloat16* wb2b = (__nv_bfloat16*)symaddr(g_wb2b);
    __nv_bfloat16* wb3b = (__nv_bfloat16*)symaddr(g_wb3b);
    __nv_bfloat16* wbd1 = (__nv_bfloat16*)symaddr(g_wbd1);
    __nv_bfloat16* wbd2 = (__nv_bfloat16*)symaddr(g_wbd2);

    const int SM128 = 3 * (128*128 + 128*128);   // 98304 (CTA 128x128)
    const int SM64  = 3 * (256*128 + 64*128);    // 122880 (CTA 256x64)

    static int attr_done = 0;
    if (!attr_done) {
        cudaFuncSetAttribute((const void*)hgemm3<LdL2,128,128,true>, cudaFuncAttributeMaxDynamicSharedMemorySize, SM128);
        cudaFuncSetAttribute((const void*)hgemm3<LdL3,64,256,false>, cudaFuncAttributeMaxDynamicSharedMemorySize, SM64);
        cudaFuncSetAttribute((const void*)hgemm3<LdD1,128,128,true>, cudaFuncAttributeMaxDynamicSharedMemorySize, SM128);
        cudaFuncSetAttribute((const void*)hgemm3<LdD2,64,256,true>,  cudaFuncAttributeMaxDynamicSharedMemorySize, SM64);
        attr_done = 1;
    }

    // #1: all weight packs + enorm + loss zero
    pack_all<<<1839, 256>>>(w1, w2, w3, dw1, dw2, emb);
    // #2: L1 im2col (NCHW direct)
    im2col_l1<<<32768, 256>>>(x, col);
    // #3: L1 fp32 GEMM, bf16 out
    { DenseLoader ld; ld.A = col; ld.ldk = 48;
      sgemm_t<<<dim3(1, 4096), 256>>>(ld, wb1, 48, mk_row(nullptr, b1, 64, 1), h1b); }
    // #4: L2 hgemm (ncu-profiled slot)
    { LdL2 ld; ld.in = h1b;
      hgemm3<LdL2,128,128,true><<<dim3(1, 1024), 128, SM128>>>(ld, wb2b, 1024,
          mk_row((float*)h2b, b2, 128, 1)); }
    // #5: L3 hgemm, fp32 z out
    { LdL3 ld; ld.in = h2b;
      hgemm3<LdL3,64,256,false><<<dim3(1, 512), 128, SM64>>>(ld, wb3b, 1152,
          mk_row(z, b3, 64, 1)); }
    // #6: VQ
    vq_fused<<<512, 256>>>(z, emb, en, qb);

    // D1: deconv 64->128, 4 parities
    for (int p = 0; p < 4; ++p) {
        LdD1 ld; ld.in = qb; ld.py = p >> 1; ld.px = p & 1;
        hgemm3<LdD1,128,128,true><<<dim3(1, 1024), 128, SM128>>>(ld, wbd1 + p * 32768, 256,
            mk_dec((float*)d1b, db1, 64*64, 64, 128, 128, p >> 1, p & 1, (long)128*128*128, 1));
    }
    // D2: deconv 128->64, 4 parities
    for (int p = 0; p < 4; ++p) {
        LdD2 ld; ld.in = d1b; ld.py = p >> 1; ld.px = p & 1;
        hgemm3<LdD2,64,256,true><<<dim3(1, 2048), 128, SM64>>>(ld, wbd2 + p * 32768, 512,
            mk_dec((float*)d2b, db2, 128*128, 128, 256, 64, p >> 1, p & 1, (long)256*256*64, 1));
    }

    // D3 + sigmoid -> NCHW out
    deconv3_sigmoid<<<dim3(4, 16, 32), 256>>>(d2b, dw3, db3, out);

    finalize_loss<<<1, 1>>>(out, (long)out_size - 1);
}

// round 13
// speedup vs baseline: 1.3365x; 1.3365x over previous
#include <cuda_runtime.h>
#include <cuda_bf16.h>
#include <cstdint>
#include <math.h>

// ---------------- device scratch ----------------
__device__ __nv_bfloat16 g_h1b[33554432];      // [32,128,128,64] NHWC bf16
__device__ __nv_bfloat16 g_h2b[16777216];      // [32,64,64,128]  NHWC bf16
__device__ float  g_z  [8388608];              // [32,64,64,64] fp32 (VQ/loss path)
__device__ __nv_bfloat16 g_qb [8388608];       // q bf16 (decoder input)
__device__ __nv_bfloat16 g_d1b[67108864];      // [32,128,128,128] bf16
__device__ __nv_bfloat16 g_d2b[134217728];     // [32,256,256,64]  bf16
__device__ float  g_col[25165824];             // L1 im2col (fp32)
__device__ float  g_wb1[3072];
__device__ __nv_bfloat16 g_wb2b[131072];
__device__ __nv_bfloat16 g_wb3b[73728];
__device__ __nv_bfloat16 g_wbd1[131072];       // 4 parities x 32768
__device__ __nv_bfloat16 g_wbd2[131072];       // 4 parities x 32768
__device__ float  g_enorm[512];
__device__ double g_loss;

__device__ __forceinline__ uint32_t smem_u32(const void* p) {
    uint32_t a;
    asm("{ .reg .u64 t; cvta.to.shared.u64 t, %1; cvt.u32.u64 %0, t; }" : "=r"(a) : "l"(p));
    return a;
}
__device__ __forceinline__ uint32_t swz(uint32_t off) { return off ^ ((off >> 3) & 0x70); }
__device__ __forceinline__ void cpa16(uint32_t dst, const void* src, bool ok) {
    asm volatile("cp.async.cg.shared.global [%0], [%1], 16, %2;"
                 :: "r"(dst), "l"(src), "r"(ok ? 16 : 0) : "memory");
}
__device__ __forceinline__ void cpa_commit() {
    asm volatile("cp.async.commit_group;" ::: "memory");
}
template<int N>
__device__ __forceinline__ void cpa_wait() {
    asm volatile("cp.async.wait_group %0;" :: "n"(N) : "memory");
}
__device__ __forceinline__ void ffma2(unsigned long long& d, unsigned long long a,
                                      unsigned long long b) {
    asm("fma.rn.f32x2 %0, %1, %2, %0;" : "+l"(d) : "l"(a), "l"(b));
}
__device__ __forceinline__ void fadd2(unsigned long long& d, unsigned long long a) {
    asm("add.rn.f32x2 %0, %0, %1;" : "+l"(d) : "l"(a));
}

// ---------------- pack_all ----------------
__global__ void __launch_bounds__(256)
pack_all(const float* __restrict__ w1, const float* __restrict__ w2,
         const float* __restrict__ w3, const float* __restrict__ dw1,
         const float* __restrict__ dw2, const float* __restrict__ emb) {
    long idx = (long)blockIdx.x * 256 + threadIdx.x;
    if (idx < 3072) {
        int co = (int)idx / 48, rem = (int)idx % 48;
        int ci = rem / 16, r2 = rem % 16;
        g_wb1[co * 48 + r2 * 3 + ci] = w1[idx];
        return;
    }
    idx -= 3072;
    if (idx < 131072) {
        int co = (int)idx >> 10, rem = (int)idx & 1023;
        int ci = rem >> 4, r2 = rem & 15;
        g_wb2b[co * 1024 + r2 * 64 + ci] = __float2bfloat16(w2[idx]);
        return;
    }
    idx -= 131072;
    if (idx < 73728) {
        int co = (int)idx / 1152, rem = (int)idx % 1152;
        int ci = rem / 9, r2 = rem % 9;
        g_wb3b[co * 1152 + r2 * 128 + ci] = __float2bfloat16(w3[idx]);
        return;
    }
    idx -= 73728;
    if (idx < 131072) {
        int p = (int)idx >> 15, local = (int)idx & 32767;
        int py = p >> 1, px = p & 1;
        int co = local >> 8, rem = local & 255;
        int ci = rem >> 2, tt = rem & 3;
        int ky = (1 - py) + 2 * (tt >> 1), kx = (1 - px) + 2 * (tt & 1);
        g_wbd1[p * 32768 + co * 256 + tt * 64 + ci] =
            __float2bfloat16(dw1[(((long)ci * 128 + co) * 4 + ky) * 4 + kx]);
        return;
    }
    idx -= 131072;
    if (idx < 131072) {
        int p = (int)idx >> 15, local = (int)idx & 32767;
        int py = p >> 1, px = p & 1;
        int co = local >> 9, rem = local & 511;
        int ci = rem >> 2, tt = rem & 3;
        int ky = (1 - py) + 2 * (tt >> 1), kx = (1 - px) + 2 * (tt & 1);
        g_wbd2[p * 32768 + co * 512 + tt * 128 + ci] =
            __float2bfloat16(dw2[(((long)ci * 64 + co) * 4 + ky) * 4 + kx]);
        return;
    }
    idx -= 131072;
    if (idx < 512) {
        float s = 0.f;
        const float* e = emb + idx * 64;
#pragma unroll 8
        for (int d = 0; d < 64; ++d) { float v = e[d]; s = fmaf(v, v, s); }
        g_enorm[idx] = s;
        return;
    }
    if (idx == 512) g_loss = 0.0;
}

__global__ void finalize_loss(float* out, long pos) {
    out[pos] = (float)(1.25 * g_loss / 8388608.0);
}

// ---------------- L1 im2col reading x NCHW directly ----------------
__global__ void __launch_bounds__(256)
im2col_l1(const float* __restrict__ x, float* __restrict__ col) {
    int mi = threadIdx.x >> 4, kt = threadIdx.x & 15;
    int m = blockIdx.x * 16 + mi;
    int n = m >> 14;
    int r = m & 16383;
    int oy = r >> 7, ox = r & 127;
    const float* xb = x + (long)n * 196608;
    float* colr = col + (long)m * 48;
    for (int k = kt; k < 48; k += 16) {
        int ci = k % 3, t = k / 3;
        int kx = t & 3, ky = t >> 2;
        int iy = oy * 2 - 1 + ky, ix = ox * 2 - 1 + kx;
        float v = 0.f;
        if (iy >= 0 && iy < 256 && ix >= 0 && ix < 256)
            v = xb[((long)ci << 16) + iy * 256 + ix];
        colr[k] = v;
    }
}

// ---------------- A-tile loaders ----------------
struct DenseLoader {
    const float* A; int ldk;
    const float* p;
    __device__ void init(int m) { p = A + (long)m * ldk; }
    __device__ void load8(int k, float4& a0, float4& a1) const {
        a0 = *(const float4*)(p + k);
        a1 = *(const float4*)(p + k + 4);
    }
};

template<int CIN, int KH, int KW, int ST, int PAD, int IH, int IW, int OW>
struct ConvLoaderB {
    const __nv_bfloat16* in;
    const __nv_bfloat16* base; int oy, ox;
    __device__ void init(int m) {
        int n = m / (OW * OW);
        int r = m % (OW * OW);
        oy = r / OW; ox = r % OW;
        base = in + (long)n * IH * IW * CIN;
    }
    __device__ const __nv_bfloat16* addr(int k, bool& ok) const {
        int ci = k % CIN, t = k / CIN;
        int ky = t / KW, kx = t % KW;
        int iy = oy * ST - PAD + ky, ix = ox * ST - PAD + kx;
        ok = (iy >= 0 && iy < IH && ix >= 0 && ix < IW);
        return ok ? base + ((long)iy * IW + ix) * CIN + ci : base;
    }
};

template<int CIN, int IH, int IW>
struct DeconvLoaderB {
    const __nv_bfloat16* in; int py, px;
    const __nv_bfloat16* base; int u, v;
    __device__ void init(int m) {
        int n = m / (IH * IW);
        int r = m % (IH * IW);
        u = r / IW; v = r % IW;
        base = in + (long)n * IH * IW * CIN;
    }
    __device__ const __nv_bfloat16* addr(int k, bool& ok) const {
        int ci = k % CIN, t = k / CIN;
        int iy = u + py - (t >> 1), ix = v + px - (t & 1);
        ok = (iy >= 0 && iy < IH && ix >= 0 && ix < IW);
        return ok ? base + ((long)iy * IW + ix) * CIN + ci : base;
    }
};

// ---------------- epilogue descriptor ----------------
struct Epi {
    float* out; const float* bias;
    int mode, act, ldc;
    int MPN, OV, W2, C, py, px;
    long nstride;
};

__device__ __forceinline__ long epi_base(const Epi& ep, int m) {
    if (ep.mode == 0) return (long)m * ep.ldc;
    int nn = m / ep.MPN, r = m % ep.MPN;
    int u = r / ep.OV, v = r % ep.OV;
    return (long)nn * ep.nstride +
           ((long)(2*u + ep.py) * ep.W2 + (2*v + ep.px)) * ep.C;
}

// ---------------- fp32 SGEMM (L1 only), bf16 output ----------------
template<class LD>
__global__ void __launch_bounds__(256)
sgemm_t(LD ld, const float* __restrict__ Bm, int K, Epi ep, __nv_bfloat16* outb) {
    __shared__ float As[16][132];
    __shared__ float Bs[16][68];
    const int tid = threadIdx.x;
    const int m0 = blockIdx.y * 128, n0 = blockIdx.x * 64;
    const int tx = tid & 15, ty = tid >> 4;
    const int ra = tid >> 1, ca = (tid & 1) * 8;
    const int rb = tid >> 2, cb = (tid & 3) * 4;
    float acc[8][4] = {};
    ld.init(m0 + ra);
    const float* Bptr = Bm + (long)(n0 + rb) * K + cb;

    for (int k0 = 0; k0 < K; k0 += 16) {
        float4 a0, a1;
        ld.load8(k0 + ca, a0, a1);
        float4 b0 = *(const float4*)(Bptr + k0);
        As[ca+0][ra]=a0.x; As[ca+1][ra]=a0.y; As[ca+2][ra]=a0.z; As[ca+3][ra]=a0.w;
        As[ca+4][ra]=a1.x; As[ca+5][ra]=a1.y; As[ca+6][ra]=a1.z; As[ca+7][ra]=a1.w;
        Bs[cb+0][rb]=b0.x; Bs[cb+1][rb]=b0.y; Bs[cb+2][rb]=b0.z; Bs[cb+3][rb]=b0.w;
        __syncthreads();
#pragma unroll
        for (int kk = 0; kk < 16; ++kk) {
            float4 aA = *(const float4*)&As[kk][ty*8];
            float4 aB = *(const float4*)&As[kk][ty*8+4];
            float4 bb = *(const float4*)&Bs[kk][tx*4];
            float av[8] = {aA.x,aA.y,aA.z,aA.w,aB.x,aB.y,aB.z,aB.w};
            float bv[4] = {bb.x,bb.y,bb.z,bb.w};
#pragma unroll
            for (int i = 0; i < 8; ++i)
#pragma unroll
                for (int j = 0; j < 4; ++j)
                    acc[i][j] = fmaf(av[i], bv[j], acc[i][j]);
        }
        __syncthreads();
    }

    const int n_base = n0 + tx * 4;
    float bvals[4];
#pragma unroll
    for (int j = 0; j < 4; ++j) bvals[j] = ep.bias ? ep.bias[n_base + j] : 0.f;
#pragma unroll
    for (int i = 0; i < 8; ++i) {
        int m = m0 + ty * 8 + i;
        long base = (long)m * ep.ldc + n_base;
        float v0 = fmaxf(acc[i][0] + bvals[0], 0.f);
        float v1 = fmaxf(acc[i][1] + bvals[1], 0.f);
        float v2 = fmaxf(acc[i][2] + bvals[2], 0.f);
        float v3 = fmaxf(acc[i][3] + bvals[3], 0.f);
        __nv_bfloat162 p0 = __floats2bfloat162_rn(v0, v1);
        __nv_bfloat162 p1 = __floats2bfloat162_rn(v2, v3);
        uint2 u; u.x = *(uint32_t*)&p0; u.y = *(uint32_t*)&p1;
        *(uint2*)(outb + base) = u;
    }
}

// ---------------- HMMA bf16 GEMM, 3-stage cp.async (128 x TN, 8 warps) — R11 ----------------
template<class LD, int TN, bool OBF>
__global__ void __launch_bounds__(256)
hgemm(LD ld, const __nv_bfloat16* __restrict__ Bw, int K, Epi ep) {
    constexpr int WN   = TN / 2;
    constexpr int NT8  = WN / 8;
    constexpr int NT16 = NT8 / 2;
    constexpr int NBC  = TN * 128 / (256 * 16);
    constexpr uint32_t ABUF = 128 * 128;
    constexpr uint32_t BBUF = (uint32_t)TN * 128;
    constexpr uint32_t STG  = ABUF + BBUF;
    extern __shared__ char dynsm[];
    const uint32_t s0 = smem_u32(dynsm);

    const int tid = threadIdx.x;
    const int wid = tid >> 5, lane = tid & 31;
    const int m0 = blockIdx.y * 128;
    const int wm = (wid >> 1) * 32;
    const int wn = (wid & 1) * WN;

    const int row = tid >> 1, half = tid & 1;
    ld.init(m0 + row);

    float acc[2][NT8][4];
#pragma unroll
    for (int i = 0; i < 2; ++i)
#pragma unroll
        for (int j = 0; j < NT8; ++j)
#pragma unroll
            for (int c = 0; c < 4; ++c) acc[i][j][c] = 0.f;

    auto fill = [&](int k0, int st) {
        bool ok;
        const __nv_bfloat16* p = ld.addr(k0 + half * 32, ok);
        uint32_t aDst = s0 + st * STG;
#pragma unroll
        for (int j = 0; j < 4; ++j) {
            uint32_t off = (uint32_t)row * 128 + half * 64 + j * 16;
            cpa16(aDst + swz(off), p + j * 8, ok);
        }
        uint32_t bDst = s0 + st * STG + ABUF;
#pragma unroll
        for (int c = 0; c < NBC; ++c) {
            int i = c * 256 + tid;
            int r = i >> 3, sg = i & 7;
            cpa16(bDst + swz((uint32_t)r * 128 + sg * 16),
                  Bw + (long)r * K + k0 + sg * 8, true);
        }
    };

    fill(0, 0);  cpa_commit();
    fill(64, 1); cpa_commit();

    int st = 0;
    for (int k0 = 0; k0 < K; k0 += 64) {
        cpa_wait<1>();
        __syncthreads();
        if (k0 + 128 < K) {
            int nst = st + 2; if (nst >= 3) nst -= 3;
            fill(k0 + 128, nst);
        }
        cpa_commit();

        const uint32_t aBase = s0 + st * STG;
        const uint32_t bBase = aBase + ABUF;
#pragma unroll
        for (int ks = 0; ks < 4; ++ks) {
            const uint32_t kb = ks * 32 + (lane >> 4) * 16;
            uint32_t af[2][4];
#pragma unroll
            for (int mi = 0; mi < 2; ++mi) {
                uint32_t r = wm + mi * 16 + (lane & 15);
                uint32_t ad = aBase + swz(r * 128 + kb);
                asm volatile("ldmatrix.sync.aligned.m8n8.x4.shared.b16 {%0,%1,%2,%3}, [%4];"
                    : "=r"(af[mi][0]), "=r"(af[mi][1]), "=r"(af[mi][2]), "=r"(af[mi][3])
                    : "r"(ad));
            }
            uint32_t bf[NT16][4];
#pragma unroll
            for (int ni = 0; ni < NT16; ++ni) {
                uint32_t r = wn + ni * 16 + (lane & 15);
                uint32_t ad = bBase + swz(r * 128 + kb);
                asm volatile("ldmatrix.sync.aligned.m8n8.x4.shared.b16 {%0,%1,%2,%3}, [%4];"
                    : "=r"(bf[ni][0]), "=r"(bf[ni][1]), "=r"(bf[ni][2]), "=r"(bf[ni][3])
                    : "r"(ad));
            }
#pragma unroll
            for (int mi = 0; mi < 2; ++mi)
#pragma unroll
                for (int ni = 0; ni < NT16; ++ni) {
                    asm volatile(
                        "mma.sync.aligned.m16n8k16.row.col.f32.bf16.bf16.f32 "
                        "{%0,%1,%2,%3}, {%4,%5,%6,%7}, {%8,%9}, {%0,%1,%2,%3};"
                        : "+f"(acc[mi][2*ni][0]), "+f"(acc[mi][2*ni][1]),
                          "+f"(acc[mi][2*ni][2]), "+f"(acc[mi][2*ni][3])
                        : "r"(af[mi][0]), "r"(af[mi][1]), "r"(af[mi][2]), "r"(af[mi][3]),
                          "r"(bf[ni][0]), "r"(bf[ni][2]));
                    asm volatile(
                        "mma.sync.aligned.m16n8k16.row.col.f32.bf16.bf16.f32 "
                        "{%0,%1,%2,%3}, {%4,%5,%6,%7}, {%8,%9}, {%0,%1,%2,%3};"
                        : "+f"(acc[mi][2*ni+1][0]), "+f"(acc[mi][2*ni+1][1]),
                          "+f"(acc[mi][2*ni+1][2]), "+f"(acc[mi][2*ni+1][3])
                        : "r"(af[mi][0]), "r"(af[mi][1]), "r"(af[mi][2]), "r"(af[mi][3]),
                          "r"(bf[ni][1]), "r"(bf[ni][3]));
                }
        }
        st = (st == 2) ? 0 : st + 1;
    }

    const int col = wn + (lane & 3) * 2;
#pragma unroll
    for (int mi = 0; mi < 2; ++mi) {
        int m1 = m0 + wm + mi * 16 + (lane >> 2);
        long b1 = epi_base(ep, m1);
        long b2 = epi_base(ep, m1 + 8);
#pragma unroll
        for (int j = 0; j < NT8; ++j) {
            int n = col + j * 8;
            float bi0 = ep.bias[n], bi1 = ep.bias[n + 1];
            float v0 = acc[mi][j][0] + bi0, v1 = acc[mi][j][1] + bi1;
            float v2 = acc[mi][j][2] + bi0, v3 = acc[mi][j][3] + bi1;
            if (ep.act) {
                v0 = fmaxf(v0, 0.f); v1 = fmaxf(v1, 0.f);
                v2 = fmaxf(v2, 0.f); v3 = fmaxf(v3, 0.f);
            }
            if (OBF) {
                __nv_bfloat16* ob = (__nv_bfloat16*)ep.out;
                __nv_bfloat162 p0 = __floats2bfloat162_rn(v0, v1);
                __nv_bfloat162 p1 = __floats2bfloat162_rn(v2, v3);
                *(uint32_t*)(ob + b1 + n) = *(uint32_t*)&p0;
                *(uint32_t*)(ob + b2 + n) = *(uint32_t*)&p1;
            } else {
                *(float2*)(ep.out + b1 + n) = make_float2(v0, v1);
                *(float2*)(ep.out + b2 + n) = make_float2(v2, v3);
            }
        }
    }
}

// ---------------- fused VQ with packed f32x2 distance math ----------------
__global__ void __launch_bounds__(256)
vq_fused(const float* __restrict__ z, const float* __restrict__ emb,
         const float* __restrict__ enorm, __nv_bfloat16* __restrict__ qb) {
    __shared__ __align__(16) unsigned long long se2[16][32];
    __shared__ float sen[16];
    __shared__ float red[256];
    const int t = threadIdx.x;
    const long m = (long)blockIdx.x * 256 + t;
    unsigned long long zr[32];
    const unsigned long long* zp = (const unsigned long long*)(z + m * 64);
#pragma unroll
    for (int i = 0; i < 32; ++i) zr[i] = zp[i];

    float best = 3.4e38f; int bidx = 0;
    const int ljj = t >> 4, ldd = t & 15;
    for (int j0 = 0; j0 < 512; j0 += 16) {
        __syncthreads();
        {
            const unsigned long long* ep = (const unsigned long long*)(emb + (long)(j0 + ljj) * 64);
            se2[ljj][ldd * 2]     = ep[ldd * 2];
            se2[ljj][ldd * 2 + 1] = ep[ldd * 2 + 1];
        }
        if (t < 16) sen[t] = enorm[j0 + t];
        __syncthreads();
#pragma unroll
        for (int jj = 0; jj < 16; ++jj) {
            unsigned long long S0 = 0ULL, S1 = 0ULL, S2 = 0ULL, S3 = 0ULL;
#pragma unroll
            for (int i = 0; i < 32; i += 4) {
                ffma2(S0, zr[i+0], se2[jj][i+0]);
                ffma2(S1, zr[i+1], se2[jj][i+1]);
                ffma2(S2, zr[i+2], se2[jj][i+2]);
                ffma2(S3, zr[i+3], se2[jj][i+3]);
            }
            fadd2(S0, S1);
            fadd2(S2, S3);
            fadd2(S0, S2);
            float lo, hi;
            asm("mov.b64 {%0,%1}, %2;" : "=f"(lo), "=f"(hi) : "l"(S0));
            float dist = sen[jj] - 2.f * (lo + hi);
            if (dist < best) { best = dist; bidx = j0 + jj; }
        }
    }

    const float4* ep4 = (const float4*)(emb + (long)bidx * 64);
    uint2* qp = (uint2*)(qb + m * 64);
    float sq = 0.f;
#pragma unroll
    for (int i = 0; i < 16; ++i) {
        float4 e = ep4[i];
        __nv_bfloat162 p0 = __floats2bfloat162_rn(e.x, e.y);
        __nv_bfloat162 p1 = __floats2bfloat162_rn(e.z, e.w);
        uint2 u; u.x = *(uint32_t*)&p0; u.y = *(uint32_t*)&p1;
        qp[i] = u;
        float z0, z1, z2, z3;
        asm("mov.b64 {%0,%1}, %2;" : "=f"(z0), "=f"(z1) : "l"(zr[2*i]));
        asm("mov.b64 {%0,%1}, %2;" : "=f"(z2), "=f"(z3) : "l"(zr[2*i+1]));
        float d0 = e.x - z0, d1 = e.y - z1;
        float d2 = e.z - z2, d3 = e.w - z3;
        sq = fmaf(d0, d0, sq); sq = fmaf(d1, d1, sq);
        sq = fmaf(d2, d2, sq); sq = fmaf(d3, d3, sq);
    }
    red[t] = sq;
    __syncthreads();
    for (int s = 128; s; s >>= 1) {
        if (t < s) red[t] += red[t + s];
        __syncthreads();
    }
    if (t == 0) atomicAdd(&g_loss, (double)red[0]);
}

// ---------------- final deconv 64->3 k3 s1 p1 + sigmoid (bf16 in, NCHW fp32 out) ----------------
__global__ void __launch_bounds__(256)
deconv3_sigmoid(const __nv_bfloat16* __restrict__ in, const float* __restrict__ w,
                const float* __restrict__ bias, float* __restrict__ out) {
    __shared__ float sIn[8][18][66];
    __shared__ float sW[1728];
    const int t = threadIdx.x, n = blockIdx.z;
    const int y0 = blockIdx.y * 16, x0 = blockIdx.x * 64;
    for (int i = t; i < 1728; i += 256) sW[i] = w[i];
    const int ty = t >> 4, txq = t & 15;
    float acc[3][4] = {};
    for (int cc = 0; cc < 8; ++cc) {
        __syncthreads();
        for (int pos = t; pos < 18 * 66; pos += 256) {
            int sx = pos % 66, sy = pos / 66;
            int gy = y0 - 1 + sy, gx = x0 - 1 + sx;
            if (gy >= 0 && gy < 256 && gx >= 0 && gx < 256) {
                uint4 u = *(const uint4*)(in + (((long)n * 256 + gy) * 256 + gx) * 64 + cc * 8);
                float2 f0 = __bfloat1622float2(*(__nv_bfloat162*)&u.x);
                float2 f1 = __bfloat1622float2(*(__nv_bfloat162*)&u.y);
                float2 f2 = __bfloat1622float2(*(__nv_bfloat162*)&u.z);
                float2 f3 = __bfloat1622float2(*(__nv_bfloat162*)&u.w);
                sIn[0][sy][sx] = f0.x; sIn[1][sy][sx] = f0.y;
                sIn[2][sy][sx] = f1.x; sIn[3][sy][sx] = f1.y;
                sIn[4][sy][sx] = f2.x; sIn[5][sy][sx] = f2.y;
                sIn[6][sy][sx] = f3.x; sIn[7][sy][sx] = f3.y;
            } else {
#pragma unroll
                for (int c = 0; c < 8; ++c) sIn[c][sy][sx] = 0.f;
            }
        }
        __syncthreads();
#pragma unroll
        for (int c8 = 0; c8 < 8; ++c8) {
            const int ci = cc * 8 + c8;
#pragma unroll
            for (int ky = 0; ky < 3; ++ky)
#pragma unroll
            for (int kx = 0; kx < 3; ++kx) {
                const float* wp = &sW[ci*27 + ky*3 + kx];
                float w0 = wp[0], w1 = wp[9], w2 = wp[18];
                const float* ip = &sIn[c8][ty + 2 - ky][txq*4 + 2 - kx];
#pragma unroll
                for (int qq = 0; qq < 4; ++qq) {
                    float iv = ip[qq];
                    acc[0][qq] = fmaf(iv, w0, acc[0][qq]);
                    acc[1][qq] = fmaf(iv, w1, acc[1][qq]);
                    acc[2][qq] = fmaf(iv, w2, acc[2][qq]);
                }
            }
        }
    }
#pragma unroll
    for (int co = 0; co < 3; ++co) {
        float bb = bias[co];
#pragma unroll
        for (int qq = 0; qq < 4; ++qq) {
            float v = acc[co][qq] + bb;
            v = 1.f / (1.f + __expf(-v));
            out[(((long)n * 3 + co) * 256 + (y0 + ty)) * 256 + (x0 + txq*4 + qq)] = v;
        }
    }
}

// ---------------- host ----------------
static float* symaddr(const void* sym) {
    void* p = nullptr;
    cudaGetSymbolAddress(&p, sym);
    return (float*)p;
}

static Epi mk_row(float* out, const float* bias, int ldc, int act) {
    Epi e; e.out = out; e.bias = bias; e.mode = 0; e.act = act; e.ldc = ldc;
    e.MPN = e.OV = e.W2 = e.C = e.py = e.px = 0; e.nstride = 0; return e;
}
static Epi mk_dec(float* out, const float* bias, int MPN, int OV, int W2, int C,
                  int py, int px, long nstride, int act) {
    Epi e; e.out = out; e.bias = bias; e.mode = 1; e.act = act; e.ldc = 0;
    e.MPN = MPN; e.OV = OV; e.W2 = W2; e.C = C; e.py = py; e.px = px;
    e.nstride = nstride; return e;
}

typedef ConvLoaderB<64,4,4,2,1,128,128,64>   LdL2;
typedef ConvLoaderB<128,3,3,1,1,64,64,64>    LdL3;
typedef DeconvLoaderB<64,64,64>              LdD1;
typedef DeconvLoaderB<128,128,128>           LdD2;

extern "C" void kernel_launch(void* const* d_in, const int* in_sizes, int n_in,
                              void* d_out, int out_size) {
    const float* x   = (const float*)d_in[0];
    const float* w1  = (const float*)d_in[1];
    const float* b1  = (const float*)d_in[2];
    const float* w2  = (const float*)d_in[3];
    const float* b2  = (const float*)d_in[4];
    const float* w3  = (const float*)d_in[5];
    const float* b3  = (const float*)d_in[6];
    const float* emb = (const float*)d_in[7];
    const float* dw1 = (const float*)d_in[8];
    const float* db1 = (const float*)d_in[9];
    const float* dw2 = (const float*)d_in[10];
    const float* db2 = (const float*)d_in[11];
    const float* dw3 = (const float*)d_in[12];
    const float* db3 = (const float*)d_in[13];
    float* out = (float*)d_out;

    float* z   = symaddr(g_z);
    float* col = symaddr(g_col);
    float* wb1 = symaddr(g_wb1);
    float* en  = symaddr(g_enorm);
    __nv_bfloat16* h1b = (__nv_bfloat16*)symaddr(g_h1b);
    __nv_bfloat16* h2b = (__nv_bfloat16*)symaddr(g_h2b);
    __nv_bfloat16* qb  = (__nv_bfloat16*)symaddr(g_qb);
    __nv_bfloat16* d1b = (__nv_bfloat16*)symaddr(g_d1b);
    __nv_bfloat16* d2b = (__nv_bfloat16*)symaddr(g_d2b);
    __nv_bfloat16* wb2b = (__nv_bfloat16*)symaddr(g_wb2b);
    __nv_bfloat16* wb3b = (__nv_bfloat16*)symaddr(g_wb3b);
    __nv_bfloat16* wbd1 = (__nv_bfloat16*)symaddr(g_wbd1);
    __nv_bfloat16* wbd2 = (__nv_bfloat16*)symaddr(g_wbd2);

    const int SM128 = 3 * (128*128 + 128*128);   // 98304
    const int SM64  = 3 * (128*128 + 64*128);    // 73728

    static int attr_done = 0;
    if (!attr_done) {
        cudaFuncSetAttribute((const void*)hgemm<LdL2,128,true>, cudaFuncAttributeMaxDynamicSharedMemorySize, SM128);
        cudaFuncSetAttribute((const void*)hgemm<LdL3,64,false>, cudaFuncAttributeMaxDynamicSharedMemorySize, SM64);
        cudaFuncSetAttribute((const void*)hgemm<LdD1,128,true>, cudaFuncAttributeMaxDynamicSharedMemorySize, SM128);
        cudaFuncSetAttribute((const void*)hgemm<LdD2,64,true>,  cudaFuncAttributeMaxDynamicSharedMemorySize, SM64);
        attr_done = 1;
    }

    // #1: all weight packs + enorm + loss zero
    pack_all<<<1839, 256>>>(w1, w2, w3, dw1, dw2, emb);
    // #2: L1 im2col (NCHW direct)
    im2col_l1<<<32768, 256>>>(x, col);
    // #3: L1 fp32 GEMM, bf16 out
    { DenseLoader ld; ld.A = col; ld.ldk = 48;
      sgemm_t<<<dim3(1, 4096), 256>>>(ld, wb1, 48, mk_row(nullptr, b1, 64, 1), h1b); }
    // #4: L2 hgemm (ncu-profiled slot)
    { LdL2 ld; ld.in = h1b;
      hgemm<LdL2,128,true><<<dim3(1, 1024), 256, SM128>>>(ld, wb2b, 1024,
          mk_row((float*)h2b, b2, 128, 1)); }
    // #5: L3 hgemm, fp32 z out
    { LdL3 ld; ld.in = h2b;
      hgemm<LdL3,64,false><<<dim3(1, 1024), 256, SM64>>>(ld, wb3b, 1152,
          mk_row(z, b3, 64, 1)); }
    // #6: VQ
    vq_fused<<<512, 256>>>(z, emb, en, qb);

    // D1: deconv 64->128, 4 parities
    for (int p = 0; p < 4; ++p) {
        LdD1 ld; ld.in = qb; ld.py = p >> 1; ld.px = p & 1;
        hgemm<LdD1,128,true><<<dim3(1, 1024), 256, SM128>>>(ld, wbd1 + p * 32768, 256,
            mk_dec((float*)d1b, db1, 64*64, 64, 128, 128, p >> 1, p & 1, (long)128*128*128, 1));
    }
    // D2: deconv 128->64, 4 parities
    for (int p = 0; p < 4; ++p) {
        LdD2 ld; ld.in = d1b; ld.py = p >> 1; ld.px = p & 1;
        hgemm<LdD2,64,true><<<dim3(1, 4096), 256, SM64>>>(ld, wbd2 + p * 32768, 512,
            mk_dec((float*)d2b, db2, 128*128, 128, 256, 64, p >> 1, p & 1, (long)256*256*64, 1));
    }

    // D3 + sigmoid -> NCHW out
    deconv3_sigmoid<<<dim3(4, 16, 32), 256>>>(d2b, dw3, db3, out);

    finalize_loss<<<1, 1>>>(out, (long)out_size - 1);
}

// round 15
// speedup vs baseline: 1.4011x; 1.0484x over previous
#include <cuda_runtime.h>
#include <cuda_bf16.h>
#include <cstdint>
#include <math.h>

// ---------------- device scratch ----------------
__device__ __nv_bfloat16 g_h1b[33554432];      // [32,128,128,64] NHWC bf16
__device__ __nv_bfloat16 g_h2b[16777216];      // [32,64,64,128]  NHWC bf16
__device__ float  g_z  [8388608];              // fp32 (VQ/loss path)
__device__ __nv_bfloat16 g_qb [8388608];
__device__ __nv_bfloat16 g_d1b[67108864];
__device__ __nv_bfloat16 g_d2b[134217728];
__device__ __nv_bfloat16 g_colb[33554432];     // L1 im2col bf16, K padded to 64
__device__ __nv_bfloat16 g_wb1b[8192];         // 64x64 padded (+ prefetch slack)
__device__ __nv_bfloat16 g_wb2b[131072];
__device__ __nv_bfloat16 g_wb3b[73728];
__device__ __nv_bfloat16 g_wbd1[131072];       // 4 parities x 32768
__device__ __nv_bfloat16 g_wbd2[131072];
__device__ float  g_enorm[512];
__device__ double g_loss;

__device__ __forceinline__ uint32_t smem_u32(const void* p) {
    uint32_t a;
    asm("{ .reg .u64 t; cvta.to.shared.u64 t, %1; cvt.u32.u64 %0, t; }" : "=r"(a) : "l"(p));
    return a;
}
__device__ __forceinline__ uint32_t swz(uint32_t off) { return off ^ ((off >> 3) & 0x70); }
__device__ __forceinline__ void cpa16(uint32_t dst, const void* src, bool ok) {
    asm volatile("cp.async.cg.shared.global [%0], [%1], 16, %2;"
                 :: "r"(dst), "l"(src), "r"(ok ? 16 : 0) : "memory");
}
__device__ __forceinline__ void cpa_commit() {
    asm volatile("cp.async.commit_group;" ::: "memory");
}
template<int N>
__device__ __forceinline__ void cpa_wait() {
    asm volatile("cp.async.wait_group %0;" :: "n"(N) : "memory");
}
__device__ __forceinline__ void ffma2(unsigned long long& d, unsigned long long a,
                                      unsigned long long b) {
    asm("fma.rn.f32x2 %0, %1, %2, %0;" : "+l"(d) : "l"(a), "l"(b));
}
__device__ __forceinline__ void fadd2(unsigned long long& d, unsigned long long a) {
    asm("add.rn.f32x2 %0, %0, %1;" : "+l"(d) : "l"(a));
}

// ---------------- pack_all ----------------
// Total index space: 4096 + 131072 + 73728 + 131072 + 131072 + 512 + 1 = 471553
// -> MUST be launched with >= 471553 threads (1843 blocks of 256).
__global__ void __launch_bounds__(256)
pack_all(const float* __restrict__ w1, const float* __restrict__ w2,
         const float* __restrict__ w3, const float* __restrict__ dw1,
         const float* __restrict__ dw2, const float* __restrict__ emb) {
    long idx = (long)blockIdx.x * 256 + threadIdx.x;
    if (idx < 4096) {                            // wb1b: 64 x 64 (K padded from 48)
        int co = (int)idx >> 6, k = (int)idx & 63;
        float v = 0.f;
        if (k < 48) {
            int ci = k % 3, t = k / 3;
            int ky = t >> 2, kx = t & 3;
            v = w1[(((long)co * 3 + ci) * 4 + ky) * 4 + kx];
        }
        g_wb1b[idx] = __float2bfloat16(v);
        return;
    }
    idx -= 4096;
    if (idx < 131072) {
        int co = (int)idx >> 10, rem = (int)idx & 1023;
        int ci = rem >> 4, r2 = rem & 15;
        g_wb2b[co * 1024 + r2 * 64 + ci] = __float2bfloat16(w2[idx]);
        return;
    }
    idx -= 131072;
    if (idx < 73728) {
        int co = (int)idx / 1152, rem = (int)idx % 1152;
        int ci = rem / 9, r2 = rem % 9;
        g_wb3b[co * 1152 + r2 * 128 + ci] = __float2bfloat16(w3[idx]);
        return;
    }
    idx -= 73728;
    if (idx < 131072) {
        int p = (int)idx >> 15, local = (int)idx & 32767;
        int py = p >> 1, px = p & 1;
        int co = local >> 8, rem = local & 255;
        int ci = rem >> 2, tt = rem & 3;
        int ky = (1 - py) + 2 * (tt >> 1), kx = (1 - px) + 2 * (tt & 1);
        g_wbd1[p * 32768 + co * 256 + tt * 64 + ci] =
            __float2bfloat16(dw1[(((long)ci * 128 + co) * 4 + ky) * 4 + kx]);
        return;
    }
    idx -= 131072;
    if (idx < 131072) {
        int p = (int)idx >> 15, local = (int)idx & 32767;
        int py = p >> 1, px = p & 1;
        int co = local >> 9, rem = local & 511;
        int ci = rem >> 2, tt = rem & 3;
        int ky = (1 - py) + 2 * (tt >> 1), kx = (1 - px) + 2 * (tt & 1);
        g_wbd2[p * 32768 + co * 512 + tt * 128 + ci] =
            __float2bfloat16(dw2[(((long)ci * 64 + co) * 4 + ky) * 4 + kx]);
        return;
    }
    idx -= 131072;
    if (idx < 512) {
        float s = 0.f;
        const float* e = emb + idx * 64;
#pragma unroll 8
        for (int d = 0; d < 64; ++d) { float v = e[d]; s = fmaf(v, v, s); }
        g_enorm[idx] = s;
        return;
    }
    if (idx == 512) g_loss = 0.0;
}

__global__ void finalize_loss(float* out, long pos) {
    out[pos] = (float)(1.25 * g_loss / 8388608.0);
}

// ---------------- L1 im2col: x NCHW fp32 -> col bf16 [M,64] (K 48 padded) ----------------
__global__ void __launch_bounds__(256)
im2col_l1(const float* __restrict__ x, __nv_bfloat16* __restrict__ col) {
    int mi = threadIdx.x >> 4, kt = threadIdx.x & 15;
    int m = blockIdx.x * 16 + mi;
    int n = m >> 14;
    int r = m & 16383;
    int oy = r >> 7, ox = r & 127;
    const float* xb = x + (long)n * 196608;
    __nv_bfloat16* colr = col + (long)m * 64;
#pragma unroll
    for (int k = kt; k < 64; k += 16) {
        float v = 0.f;
        if (k < 48) {
            int ci = k % 3, t = k / 3;
            int kx = t & 3, ky = t >> 2;
            int iy = oy * 2 - 1 + ky, ix = ox * 2 - 1 + kx;
            if (iy >= 0 && iy < 256 && ix >= 0 && ix < 256)
                v = xb[((long)ci << 16) + iy * 256 + ix];
        }
        colr[k] = __float2bfloat16(v);
    }
}

// ---------------- A-tile loaders (bf16, addr-producing) ----------------
struct DenseLoaderB {
    const __nv_bfloat16* A; int ldk;
    long moff;
    __device__ void set_parity(int, int) {}
    __device__ void init(int m) { moff = (long)m * ldk; }
    __device__ const __nv_bfloat16* addr(int k, bool& ok) const {
        ok = true;
        return A + moff + k;
    }
};

template<int CIN, int KH, int KW, int ST, int PAD, int IH, int IW, int OW>
struct ConvLoaderB {
    const __nv_bfloat16* in;
    const __nv_bfloat16* base; int oy, ox;
    __device__ void set_parity(int, int) {}
    __device__ void init(int m) {
        int n = m / (OW * OW);
        int r = m % (OW * OW);
        oy = r / OW; ox = r % OW;
        base = in + (long)n * IH * IW * CIN;
    }
    __device__ const __nv_bfloat16* addr(int k, bool& ok) const {
        int ci = k % CIN, t = k / CIN;
        int ky = t / KW, kx = t % KW;
        int iy = oy * ST - PAD + ky, ix = ox * ST - PAD + kx;
        ok = (iy >= 0 && iy < IH && ix >= 0 && ix < IW);
        return ok ? base + ((long)iy * IW + ix) * CIN + ci : base;
    }
};

template<int CIN, int IH, int IW>
struct DeconvLoaderB {
    const __nv_bfloat16* in; int py, px;
    const __nv_bfloat16* base; int u, v;
    __device__ void set_parity(int a, int b) { py = a; px = b; }
    __device__ void init(int m) {
        int n = m / (IH * IW);
        int r = m % (IH * IW);
        u = r / IW; v = r % IW;
        base = in + (long)n * IH * IW * CIN;
    }
    __device__ const __nv_bfloat16* addr(int k, bool& ok) const {
        int ci = k % CIN, t = k / CIN;
        int iy = u + py - (t >> 1), ix = v + px - (t & 1);
        ok = (iy >= 0 && iy < IH && ix >= 0 && ix < IW);
        return ok ? base + ((long)iy * IW + ix) * CIN + ci : base;
    }
};

// ---------------- epilogue descriptor ----------------
struct Epi {
    float* out; const float* bias;
    int mode, act, ldc;
    int MPN, OV, W2, C, py, px;
    long nstride;
};

__device__ __forceinline__ long epi_base(const Epi& ep, int m) {
    if (ep.mode == 0) return (long)m * ep.ldc;
    int nn = m / ep.MPN, r = m % ep.MPN;
    int u = r / ep.OV, v = r % ep.OV;
    return (long)nn * ep.nstride +
           ((long)(2*u + ep.py) * ep.W2 + (2*v + ep.px)) * ep.C;
}

// ---------------- HMMA bf16 GEMM, 3-stage cp.async (128 x TN, 8 warps) ----------------
// wstride != 0: blockIdx.z = deconv parity (weights offset + py/px in-kernel).
template<class LD, int TN, bool OBF>
__global__ void __launch_bounds__(256)
hgemm(LD ld, const __nv_bfloat16* __restrict__ Bw, int K, Epi ep, int wstride) {
    constexpr int WN   = TN / 2;
    constexpr int NT8  = WN / 8;
    constexpr int NT16 = NT8 / 2;
    constexpr int NBC  = TN * 128 / (256 * 16);
    constexpr uint32_t ABUF = 128 * 128;
    constexpr uint32_t BBUF = (uint32_t)TN * 128;
    constexpr uint32_t STG  = ABUF + BBUF;
    extern __shared__ char dynsm[];
    const uint32_t s0 = smem_u32(dynsm);

    if (wstride) {
        int p = blockIdx.z;
        Bw += (long)p * wstride;
        ep.py = p >> 1; ep.px = p & 1;
        ld.set_parity(p >> 1, p & 1);
    }

    const int tid = threadIdx.x;
    const int wid = tid >> 5, lane = tid & 31;
    const int m0 = blockIdx.y * 128;
    const int wm = (wid >> 1) * 32;
    const int wn = (wid & 1) * WN;

    const int row = tid >> 1, half = tid & 1;
    ld.init(m0 + row);

    float acc[2][NT8][4];
#pragma unroll
    for (int i = 0; i < 2; ++i)
#pragma unroll
        for (int j = 0; j < NT8; ++j)
#pragma unroll
            for (int c = 0; c < 4; ++c) acc[i][j][c] = 0.f;

    auto fill = [&](int k0, int st) {
        bool ok;
        const __nv_bfloat16* p = ld.addr(k0 + half * 32, ok);
        uint32_t aDst = s0 + st * STG;
#pragma unroll
        for (int j = 0; j < 4; ++j) {
            uint32_t off = (uint32_t)row * 128 + half * 64 + j * 16;
            cpa16(aDst + swz(off), p + j * 8, ok);
        }
        uint32_t bDst = s0 + st * STG + ABUF;
#pragma unroll
        for (int c = 0; c < NBC; ++c) {
            int i = c * 256 + tid;
            int r = i >> 3, sg = i & 7;
            cpa16(bDst + swz((uint32_t)r * 128 + sg * 16),
                  Bw + (long)r * K + k0 + sg * 8, true);
        }
    };

    fill(0, 0);  cpa_commit();
    fill(64, 1); cpa_commit();

    int st = 0;
    for (int k0 = 0; k0 < K; k0 += 64) {
        cpa_wait<1>();
        __syncthreads();
        if (k0 + 128 < K) {
            int nst = st + 2; if (nst >= 3) nst -= 3;
            fill(k0 + 128, nst);
        }
        cpa_commit();

        const uint32_t aBase = s0 + st * STG;
        const uint32_t bBase = aBase + ABUF;
#pragma unroll
        for (int ks = 0; ks < 4; ++ks) {
            const uint32_t kb = ks * 32 + (lane >> 4) * 16;
            uint32_t af[2][4];
#pragma unroll
            for (int mi = 0; mi < 2; ++mi) {
                uint32_t r = wm + mi * 16 + (lane & 15);
                uint32_t ad = aBase + swz(r * 128 + kb);
                asm volatile("ldmatrix.sync.aligned.m8n8.x4.shared.b16 {%0,%1,%2,%3}, [%4];"
                    : "=r"(af[mi][0]), "=r"(af[mi][1]), "=r"(af[mi][2]), "=r"(af[mi][3])
                    : "r"(ad));
            }
            uint32_t bf[NT16][4];
#pragma unroll
            for (int ni = 0; ni < NT16; ++ni) {
                uint32_t r = wn + ni * 16 + (lane & 15);
                uint32_t ad = bBase + swz(r * 128 + kb);
                asm volatile("ldmatrix.sync.aligned.m8n8.x4.shared.b16 {%0,%1,%2,%3}, [%4];"
                    : "=r"(bf[ni][0]), "=r"(bf[ni][1]), "=r"(bf[ni][2]), "=r"(bf[ni][3])
                    : "r"(ad));
            }
#pragma unroll
            for (int mi = 0; mi < 2; ++mi)
#pragma unroll
                for (int ni = 0; ni < NT16; ++ni) {
                    asm volatile(
                        "mma.sync.aligned.m16n8k16.row.col.f32.bf16.bf16.f32 "
                        "{%0,%1,%2,%3}, {%4,%5,%6,%7}, {%8,%9}, {%0,%1,%2,%3};"
                        : "+f"(acc[mi][2*ni][0]), "+f"(acc[mi][2*ni][1]),
                          "+f"(acc[mi][2*ni][2]), "+f"(acc[mi][2*ni][3])
                        : "r"(af[mi][0]), "r"(af[mi][1]), "r"(af[mi][2]), "r"(af[mi][3]),
                          "r"(bf[ni][0]), "r"(bf[ni][2]));
                    asm volatile(
                        "mma.sync.aligned.m16n8k16.row.col.f32.bf16.bf16.f32 "
                        "{%0,%1,%2,%3}, {%4,%5,%6,%7}, {%8,%9}, {%0,%1,%2,%3};"
                        : "+f"(acc[mi][2*ni+1][0]), "+f"(acc[mi][2*ni+1][1]),
                          "+f"(acc[mi][2*ni+1][2]), "+f"(acc[mi][2*ni+1][3])
                        : "r"(af[mi][0]), "r"(af[mi][1]), "r"(af[mi][2]), "r"(af[mi][3]),
                          "r"(bf[ni][1]), "r"(bf[ni][3]));
                }
        }
        st = (st == 2) ? 0 : st + 1;
    }

    const int col = wn + (lane & 3) * 2;
#pragma unroll
    for (int mi = 0; mi < 2; ++mi) {
        int m1 = m0 + wm + mi * 16 + (lane >> 2);
        long b1 = epi_base(ep, m1);
        long b2 = epi_base(ep, m1 + 8);
#pragma unroll
        for (int j = 0; j < NT8; ++j) {
            int n = col + j * 8;
            float bi0 = ep.bias[n], bi1 = ep.bias[n + 1];
            float v0 = acc[mi][j][0] + bi0, v1 = acc[mi][j][1] + bi1;
            float v2 = acc[mi][j][2] + bi0, v3 = acc[mi][j][3] + bi1;
            if (ep.act) {
                v0 = fmaxf(v0, 0.f); v1 = fmaxf(v1, 0.f);
                v2 = fmaxf(v2, 0.f); v3 = fmaxf(v3, 0.f);
            }
            if (OBF) {
                __nv_bfloat16* ob = (__nv_bfloat16*)ep.out;
                __nv_bfloat162 p0 = __floats2bfloat162_rn(v0, v1);
                __nv_bfloat162 p1 = __floats2bfloat162_rn(v2, v3);
                *(uint32_t*)(ob + b1 + n) = *(uint32_t*)&p0;
                *(uint32_t*)(ob + b2 + n) = *(uint32_t*)&p1;
            } else {
                *(float2*)(ep.out + b1 + n) = make_float2(v0, v1);
                *(float2*)(ep.out + b2 + n) = make_float2(v2, v3);
            }
        }
    }
}

// ---------------- fused VQ with packed f32x2 distance math ----------------
__global__ void __launch_bounds__(256)
vq_fused(const float* __restrict__ z, const float* __restrict__ emb,
         const float* __restrict__ enorm, __nv_bfloat16* __restrict__ qb) {
    __shared__ __align__(16) unsigned long long se2[16][32];
    __shared__ float sen[16];
    __shared__ float red[256];
    const int t = threadIdx.x;
    const long m = (long)blockIdx.x * 256 + t;
    unsigned long long zr[32];
    const unsigned long long* zp = (const unsigned long long*)(z + m * 64);
#pragma unroll
    for (int i = 0; i < 32; ++i) zr[i] = zp[i];

    float best = 3.4e38f; int bidx = 0;
    const int ljj = t >> 4, ldd = t & 15;
    for (int j0 = 0; j0 < 512; j0 += 16) {
        __syncthreads();
        {
            const unsigned long long* ep = (const unsigned long long*)(emb + (long)(j0 + ljj) * 64);
            se2[ljj][ldd * 2]     = ep[ldd * 2];
            se2[ljj][ldd * 2 + 1] = ep[ldd * 2 + 1];
        }
        if (t < 16) sen[t] = enorm[j0 + t];
        __syncthreads();
#pragma unroll
        for (int jj = 0; jj < 16; ++jj) {
            unsigned long long S0 = 0ULL, S1 = 0ULL, S2 = 0ULL, S3 = 0ULL;
#pragma unroll
            for (int i = 0; i < 32; i += 4) {
                ffma2(S0, zr[i+0], se2[jj][i+0]);
                ffma2(S1, zr[i+1], se2[jj][i+1]);
                ffma2(S2, zr[i+2], se2[jj][i+2]);
                ffma2(S3, zr[i+3], se2[jj][i+3]);
            }
            fadd2(S0, S1);
            fadd2(S2, S3);
            fadd2(S0, S2);
            float lo, hi;
            asm("mov.b64 {%0,%1}, %2;" : "=f"(lo), "=f"(hi) : "l"(S0));
            float dist = sen[jj] - 2.f * (lo + hi);
            if (dist < best) { best = dist; bidx = j0 + jj; }
        }
    }

    const float4* ep4 = (const float4*)(emb + (long)bidx * 64);
    uint2* qp = (uint2*)(qb + m * 64);
    float sq = 0.f;
#pragma unroll
    for (int i = 0; i < 16; ++i) {
        float4 e = ep4[i];
        __nv_bfloat162 p0 = __floats2bfloat162_rn(e.x, e.y);
        __nv_bfloat162 p1 = __floats2bfloat162_rn(e.z, e.w);
        uint2 u; u.x = *(uint32_t*)&p0; u.y = *(uint32_t*)&p1;
        qp[i] = u;
        float z0, z1, z2, z3;
        asm("mov.b64 {%0,%1}, %2;" : "=f"(z0), "=f"(z1) : "l"(zr[2*i]));
        asm("mov.b64 {%0,%1}, %2;" : "=f"(z2), "=f"(z3) : "l"(zr[2*i+1]));
        float d0 = e.x - z0, d1 = e.y - z1;
        float d2 = e.z - z2, d3 = e.w - z3;
        sq = fmaf(d0, d0, sq); sq = fmaf(d1, d1, sq);
        sq = fmaf(d2, d2, sq); sq = fmaf(d3, d3, sq);
    }
    red[t] = sq;
    __syncthreads();
    for (int s = 128; s; s >>= 1) {
        if (t < s) red[t] += red[t + s];
        __syncthreads();
    }
    if (t == 0) atomicAdd(&g_loss, (double)red[0]);
}

// ---------------- final deconv 64->3 k3 s1 p1 + sigmoid (bf16 in, NCHW fp32 out) ----------------
__global__ void __launch_bounds__(256)
deconv3_sigmoid(const __nv_bfloat16* __restrict__ in, const float* __restrict__ w,
                const float* __restrict__ bias, float* __restrict__ out) {
    __shared__ float sIn[8][18][66];
    __shared__ float sW[1728];
    const int t = threadIdx.x, n = blockIdx.z;
    const int y0 = blockIdx.y * 16, x0 = blockIdx.x * 64;
    for (int i = t; i < 1728; i += 256) sW[i] = w[i];
    const int ty = t >> 4, txq = t & 15;
    float acc[3][4] = {};
    for (int cc = 0; cc < 8; ++cc) {
        __syncthreads();
        for (int pos = t; pos < 18 * 66; pos += 256) {
            int sx = pos % 66, sy = pos / 66;
            int gy = y0 - 1 + sy, gx = x0 - 1 + sx;
            if (gy >= 0 && gy < 256 && gx >= 0 && gx < 256) {
                uint4 u = *(const uint4*)(in + (((long)n * 256 + gy) * 256 + gx) * 64 + cc * 8);
                float2 f0 = __bfloat1622float2(*(__nv_bfloat162*)&u.x);
                float2 f1 = __bfloat1622float2(*(__nv_bfloat162*)&u.y);
                float2 f2 = __bfloat1622float2(*(__nv_bfloat162*)&u.z);
                float2 f3 = __bfloat1622float2(*(__nv_bfloat162*)&u.w);
                sIn[0][sy][sx] = f0.x; sIn[1][sy][sx] = f0.y;
                sIn[2][sy][sx] = f1.x; sIn[3][sy][sx] = f1.y;
                sIn[4][sy][sx] = f2.x; sIn[5][sy][sx] = f2.y;
                sIn[6][sy][sx] = f3.x; sIn[7][sy][sx] = f3.y;
            } else {
#pragma unroll
                for (int c = 0; c < 8; ++c) sIn[c][sy][sx] = 0.f;
            }
        }
        __syncthreads();
#pragma unroll
        for (int c8 = 0; c8 < 8; ++c8) {
            const int ci = cc * 8 + c8;
#pragma unroll
            for (int ky = 0; ky < 3; ++ky)
#pragma unroll
            for (int kx = 0; kx < 3; ++kx) {
                const float* wp = &sW[ci*27 + ky*3 + kx];
                float w0 = wp[0], w1 = wp[9], w2 = wp[18];
                const float* ip = &sIn[c8][ty + 2 - ky][txq*4 + 2 - kx];
#pragma unroll
                for (int qq = 0; qq < 4; ++qq) {
                    float iv = ip[qq];
                    acc[0][qq] = fmaf(iv, w0, acc[0][qq]);
                    acc[1][qq] = fmaf(iv, w1, acc[1][qq]);
                    acc[2][qq] = fmaf(iv, w2, acc[2][qq]);
                }
            }
        }
    }
#pragma unroll
    for (int co = 0; co < 3; ++co) {
        float bb = bias[co];
#pragma unroll
        for (int qq = 0; qq < 4; ++qq) {
            float v = acc[co][qq] + bb;
            v = 1.f / (1.f + __expf(-v));
            out[(((long)n * 3 + co) * 256 + (y0 + ty)) * 256 + (x0 + txq*4 + qq)] = v;
        }
    }
}

// ---------------- host ----------------
static float* symaddr(const void* sym) {
    void* p = nullptr;
    cudaGetSymbolAddress(&p, sym);
    return (float*)p;
}

static Epi mk_row(float* out, const float* bias, int ldc, int act) {
    Epi e; e.out = out; e.bias = bias; e.mode = 0; e.act = act; e.ldc = ldc;
    e.MPN = e.OV = e.W2 = e.C = e.py = e.px = 0; e.nstride = 0; return e;
}
static Epi mk_dec(float* out, const float* bias, int MPN, int OV, int W2, int C,
                  long nstride, int act) {
    Epi e; e.out = out; e.bias = bias; e.mode = 1; e.act = act; e.ldc = 0;
    e.MPN = MPN; e.OV = OV; e.W2 = W2; e.C = C; e.py = 0; e.px = 0;
    e.nstride = nstride; return e;
}

typedef ConvLoaderB<64,4,4,2,1,128,128,64>   LdL2;
typedef ConvLoaderB<128,3,3,1,1,64,64,64>    LdL3;
typedef DeconvLoaderB<64,64,64>              LdD1;
typedef DeconvLoaderB<128,128,128>           LdD2;

extern "C" void kernel_launch(void* const* d_in, const int* in_sizes, int n_in,
                              void* d_out, int out_size) {
    const float* x   = (const float*)d_in[0];
    const float* w1  = (const float*)d_in[1];
    const float* b1  = (const float*)d_in[2];
    const float* w2  = (const float*)d_in[3];
    const float* b2  = (const float*)d_in[4];
    const float* w3  = (const float*)d_in[5];
    const float* b3  = (const float*)d_in[6];
    const float* emb = (const float*)d_in[7];
    const float* dw1 = (const float*)d_in[8];
    const float* db1 = (const float*)d_in[9];
    const float* dw2 = (const float*)d_in[10];
    const float* db2 = (const float*)d_in[11];
    const float* dw3 = (const float*)d_in[12];
    const float* db3 = (const float*)d_in[13];
    float* out = (float*)d_out;

    float* z   = symaddr(g_z);
    float* en  = symaddr(g_enorm);
    __nv_bfloat16* colb = (__nv_bfloat16*)symaddr(g_colb);
    __nv_bfloat16* h1b = (__nv_bfloat16*)symaddr(g_h1b);
    __nv_bfloat16* h2b = (__nv_bfloat16*)symaddr(g_h2b);
    __nv_bfloat16* qb  = (__nv_bfloat16*)symaddr(g_qb);
    __nv_bfloat16* d1b = (__nv_bfloat16*)symaddr(g_d1b);
    __nv_bfloat16* d2b = (__nv_bfloat16*)symaddr(g_d2b);
    __nv_bfloat16* wb1b = (__nv_bfloat16*)symaddr(g_wb1b);
    __nv_bfloat16* wb2b = (__nv_bfloat16*)symaddr(g_wb2b);
    __nv_bfloat16* wb3b = (__nv_bfloat16*)symaddr(g_wb3b);
    __nv_bfloat16* wbd1 = (__nv_bfloat16*)symaddr(g_wbd1);
    __nv_bfloat16* wbd2 = (__nv_bfloat16*)symaddr(g_wbd2);

    const int SM128 = 3 * (128*128 + 128*128);   // 98304
    const int SM64  = 3 * (128*128 + 64*128);    // 73728

    static int attr_done = 0;
    if (!attr_done) {
        cudaFuncSetAttribute((const void*)hgemm<DenseLoaderB,64,true>, cudaFuncAttributeMaxDynamicSharedMemorySize, SM64);
        cudaFuncSetAttribute((const void*)hgemm<LdL2,128,true>, cudaFuncAttributeMaxDynamicSharedMemorySize, SM128);
        cudaFuncSetAttribute((const void*)hgemm<LdL3,64,false>, cudaFuncAttributeMaxDynamicSharedMemorySize, SM64);
        cudaFuncSetAttribute((const void*)hgemm<LdD1,128,true>, cudaFuncAttributeMaxDynamicSharedMemorySize, SM128);
        cudaFuncSetAttribute((const void*)hgemm<LdD2,64,true>,  cudaFuncAttributeMaxDynamicSharedMemorySize, SM64);
        attr_done = 1;
    }

    // #1: weight packs + enorm + loss zero (1843 blocks covers idx space 471553)
    pack_all<<<1843, 256>>>(w1, w2, w3, dw1, dw2, emb);
    // #2: L1 im2col bf16 (NCHW direct, K padded 48->64)
    im2col_l1<<<32768, 256>>>(x, colb);
    // #3: L1 hgemm (M=524288, K=64, N=64)
    { DenseLoaderB ld; ld.A = colb; ld.ldk = 64;
      hgemm<DenseLoaderB,64,true><<<dim3(1, 4096), 256, SM64>>>(ld, wb1b, 64,
          mk_row((float*)h1b, b1, 64, 1), 0); }
    // #4: L2 hgemm (ncu-profiled slot)
    { LdL2 ld; ld.in = h1b;
      hgemm<LdL2,128,true><<<dim3(1, 1024), 256, SM128>>>(ld, wb2b, 1024,
          mk_row((float*)h2b, b2, 128, 1), 0); }
    // #5: L3 hgemm, fp32 z out
    { LdL3 ld; ld.in = h2b;
      hgemm<LdL3,64,false><<<dim3(1, 1024), 256, SM64>>>(ld, wb3b, 1152,
          mk_row(z, b3, 64, 1), 0); }
    // #6: VQ
    vq_fused<<<512, 256>>>(z, emb, en, qb);
    // #7: D1, all 4 parities in one launch (blockIdx.z)
    { LdD1 ld; ld.in = qb; ld.py = 0; ld.px = 0;
      hgemm<LdD1,128,true><<<dim3(1, 1024, 4), 256, SM128>>>(ld, wbd1, 256,
          mk_dec((float*)d1b, db1, 64*64, 64, 128, 128, (long)128*128*128, 1), 32768); }
    // #8: D2, all 4 parities in one launch
    { LdD2 ld; ld.in = d1b; ld.py = 0; ld.px = 0;
      hgemm<LdD2,64,true><<<dim3(1, 4096, 4), 256, SM64>>>(ld, wbd2, 512,
          mk_dec((float*)d2b, db2, 128*128, 128, 256, 64, (long)256*256*64, 1), 32768); }
    // #9: D3 + sigmoid -> NCHW out
    deconv3_sigmoid<<<dim3(4, 16, 32), 256>>>(d2b, dw3, db3, out);
    // #10: loss
    finalize_loss<<<1, 1>>>(out, (long)out_size - 1);
}